// round 9
// baseline (speedup 1.0000x reference)
#include <cuda_runtime.h>
#include <cuda_bf16.h>
#include <math.h>

#define BB 16
#define NN 512
#define HH 128
#define EE 4
#define NE 2048          /* NN*EE */
#define NR 8192          /* BB*NN */
#define STEPS 5

// ---------------- scratch (device globals; no allocation) ----------------
__device__ float g_h[NR * HH];                 // 4 MB  current hidden state
__device__ float g_in_st[BB * NE * HH];        // 16 MB in_states  (B, N*E, H)
__device__ float g_out_st[BB * NE * HH];       // 16 MB out_states
__device__ float g_ain[NR * HH];               // 4 MB
__device__ float g_aout[NR * HH];              // 4 MB
__device__ float g_z[NR * HH];                 // 4 MB
__device__ float g_rh[NR * HH];                // 4 MB  r * h

__device__ __forceinline__ float sigmoidf_(float v) { return 1.0f / (1.0f + expf(-v)); }

// ================= R2-proven fp32 SIMT GEMM core (proj/gates) =================
template <class ALoad, class BLoad, class Epi>
__device__ __forceinline__ void gemm64(ALoad aload, BLoad bload, Epi epi, int K) {
  __shared__ __align__(16) float As[16][68];
  __shared__ __align__(16) float Bs[16][64];
  float acc[4][4] = {};
  const int tid = threadIdx.x;
  const int tx = tid & 15, ty = tid >> 4;
  const int ar = tid >> 2, ak = (tid & 3) << 2;
  const int bk = tid >> 4, bn = (tid & 15) << 2;

  for (int k0 = 0; k0 < K; k0 += 16) {
    float4 av = aload(ar, k0 + ak);
    As[ak + 0][ar] = av.x;
    As[ak + 1][ar] = av.y;
    As[ak + 2][ar] = av.z;
    As[ak + 3][ar] = av.w;
    float4 bv = bload(k0 + bk, bn);
    *reinterpret_cast<float4*>(&Bs[bk][bn]) = bv;
    __syncthreads();
#pragma unroll
    for (int kk = 0; kk < 16; kk++) {
      float4 a4 = *reinterpret_cast<const float4*>(&As[kk][ty << 2]);
      float4 b4 = *reinterpret_cast<const float4*>(&Bs[kk][tx << 2]);
      float a[4] = {a4.x, a4.y, a4.z, a4.w};
      float b[4] = {b4.x, b4.y, b4.z, b4.w};
#pragma unroll
      for (int i = 0; i < 4; i++)
#pragma unroll
        for (int j = 0; j < 4; j++) acc[i][j] += a[i] * b[j];
    }
    __syncthreads();
  }
  epi(acc, ty, tx);
}

// ================= bf16-split tensor-core einsum (8-term, bias-safe) =========
__device__ __forceinline__ void mma16(float (&d)[4], const unsigned (&a)[4],
                                      unsigned b0, unsigned b1) {
  asm volatile(
      "mma.sync.aligned.m16n8k16.row.col.f32.bf16.bf16.f32 "
      "{%0,%1,%2,%3}, {%4,%5,%6,%7}, {%8,%9}, {%0,%1,%2,%3};"
      : "+f"(d[0]), "+f"(d[1]), "+f"(d[2]), "+f"(d[3])
      : "r"(a[0]), "r"(a[1]), "r"(a[2]), "r"(a[3]), "r"(b0), "r"(b1));
}

// exact 3-way bf16 split: x = b0 + b1 + b2 + O(2^-26 |x|)
__device__ __forceinline__ void split3(float x, unsigned& s0, unsigned& s1, unsigned& s2) {
  __nv_bfloat16 b0 = __float2bfloat16_rn(x);
  float r1 = x - __bfloat162float(b0);
  __nv_bfloat16 b1 = __float2bfloat16_rn(r1);
  float r2 = r1 - __bfloat162float(b1);
  __nv_bfloat16 b2 = __float2bfloat16_rn(r2);
  s0 = (unsigned)__bfloat16_as_ushort(b0);
  s1 = (unsigned)__bfloat16_as_ushort(b1);
  s2 = (unsigned)__bfloat16_as_ushort(b2);
}

#define AS 20                     /* u32 stride per A row */
#define APLANE (128 * AS)         /* 2560 u32 */
#define BSd 136                   /* u32 stride per B k2-row */
#define BPLANE (16 * BSd)         /* 2176 u32 */
#define ABUF (3 * APLANE)
#define BBUF (3 * BPLANE)
#define EIN_SMEM ((2 * (ABUF + BBUF)) * 4)   /* 113664 bytes */

// a_in[b] = m_in[b] (512x2048) @ in_states[b] (2048x128); same for out.
// CTA tile 128x128, K-chunk 32, 8 warps (4M x 2N), warp tile 32x64.
// Per 16-k slice & output fragment: 8 split-term MMAs accumulate into a
// ZEROED partial, then a round-to-nearest FADD folds it into the master
// accumulator — isolating tensor-core truncation bias to chunk scale.
__global__ __launch_bounds__(256) void einsum_tc8(const float* __restrict__ mm) {
  extern __shared__ __align__(16) unsigned smp[];
  const int zz = blockIdx.y, dir = zz & 1, b = zz >> 1;
  const int m0 = blockIdx.x << 7;
  const float* Ag = mm + (size_t)b * NN * (2 * NE) + (size_t)dir * NE;
  const float* Bg = (dir ? g_out_st : g_in_st) + (size_t)b * NE * HH;
  float* Cb = (dir ? g_aout : g_ain) + (size_t)(b * NN + m0) * HH;

  const int tid = threadIdx.x, lane = tid & 31, wid = tid >> 5;
  const int wm = (wid & 3) << 5;
  const int wn = (wid >> 2) << 6;
  const int qr = lane >> 2, qc = lane & 3;

  float acc[2][8][4] = {};
  float4 sa[4], sb0[2], sb1[2];

  auto stage = [&](int c) {
#pragma unroll
    for (int i = 0; i < 4; i++) {
      int id = tid + (i << 8);
      sa[i] = *reinterpret_cast<const float4*>(
          &Ag[(size_t)(m0 + (id >> 3)) * (2 * NE) + (c << 5) + ((id & 7) << 2)]);
    }
#pragma unroll
    for (int i = 0; i < 2; i++) {
      int id = tid + (i << 8);
      int k2 = id >> 5, n4 = (id & 31) << 2;
      sb0[i] = *reinterpret_cast<const float4*>(&Bg[(size_t)((c << 5) + (k2 << 1)) * HH + n4]);
      sb1[i] = *reinterpret_cast<const float4*>(&Bg[(size_t)((c << 5) + (k2 << 1) + 1) * HH + n4]);
    }
  };

  auto commit = [&](int bf) {
    unsigned* Ab = smp + bf * ABUF;
    unsigned* Bb = smp + 2 * ABUF + bf * BBUF;
#pragma unroll
    for (int i = 0; i < 4; i++) {
      int id = tid + (i << 8);
      int row = id >> 3, seg = id & 7;
      unsigned x0, x1, x2, y0, y1, y2, z0, z1, z2, w0, w1, w2;
      split3(sa[i].x, x0, x1, x2);
      split3(sa[i].y, y0, y1, y2);
      split3(sa[i].z, z0, z1, z2);
      split3(sa[i].w, w0, w1, w2);
      int o = row * AS + (seg << 1);
      Ab[o]                  = x0 | (y0 << 16);
      Ab[o + 1]              = z0 | (w0 << 16);
      Ab[APLANE + o]         = x1 | (y1 << 16);
      Ab[APLANE + o + 1]     = z1 | (w1 << 16);
      Ab[2 * APLANE + o]     = x2 | (y2 << 16);
      Ab[2 * APLANE + o + 1] = z2 | (w2 << 16);
    }
#pragma unroll
    for (int i = 0; i < 2; i++) {
      int id = tid + (i << 8);
      int k2 = id >> 5, n4 = (id & 31) << 2;
      float lo[4] = {sb0[i].x, sb0[i].y, sb0[i].z, sb0[i].w};
      float hi[4] = {sb1[i].x, sb1[i].y, sb1[i].z, sb1[i].w};
      unsigned u0[4], u1[4], u2[4];
#pragma unroll
      for (int j = 0; j < 4; j++) {
        unsigned a0, a1, a2, c0, c1, c2;
        split3(lo[j], a0, a1, a2);
        split3(hi[j], c0, c1, c2);
        u0[j] = a0 | (c0 << 16);
        u1[j] = a1 | (c1 << 16);
        u2[j] = a2 | (c2 << 16);
      }
      int o = k2 * BSd + n4;
      *(uint4*)&Bb[o]              = make_uint4(u0[0], u0[1], u0[2], u0[3]);
      *(uint4*)&Bb[BPLANE + o]     = make_uint4(u1[0], u1[1], u1[2], u1[3]);
      *(uint4*)&Bb[2 * BPLANE + o] = make_uint4(u2[0], u2[1], u2[2], u2[3]);
    }
  };

  stage(0);
  commit(0);
  __syncthreads();

  const int C = NE >> 5;   // 64
  for (int c = 0; c < C; c++) {
    if (c + 1 < C) stage(c + 1);
    const unsigned* Ab = smp + (c & 1) * ABUF;
    const unsigned* Bb = smp + 2 * ABUF + (c & 1) * BBUF;
#pragma unroll
    for (int ks = 0; ks < 2; ks++) {
      unsigned af[3][2][4];
#pragma unroll
      for (int p = 0; p < 3; p++)
#pragma unroll
        for (int mi = 0; mi < 2; mi++) {
          int r = wm + (mi << 4) + qr;
          int o = (ks << 3) + qc;
          af[p][mi][0] = Ab[p * APLANE + r * AS + o];
          af[p][mi][1] = Ab[p * APLANE + (r + 8) * AS + o];
          af[p][mi][2] = Ab[p * APLANE + r * AS + o + 4];
          af[p][mi][3] = Ab[p * APLANE + (r + 8) * AS + o + 4];
        }
#pragma unroll
      for (int nj = 0; nj < 8; nj++) {
        int n = wn + (nj << 3) + qr;
        unsigned bf0[3], bf1[3];
#pragma unroll
        for (int p = 0; p < 3; p++) {
          bf0[p] = Bb[p * BPLANE + ((ks << 3) + qc) * BSd + n];
          bf1[p] = Bb[p * BPLANE + ((ks << 3) + qc + 4) * BSd + n];
        }
#pragma unroll
        for (int mi = 0; mi < 2; mi++) {
          // chunk-local partial: zero-init, 8 terms smallest-first,
          // then RN FADD into master accumulator.
          float par[4] = {0.f, 0.f, 0.f, 0.f};
          mma16(par, af[2][mi], bf0[1], bf1[1]);   // A2*B1
          mma16(par, af[1][mi], bf0[2], bf1[2]);   // A1*B2
          mma16(par, af[2][mi], bf0[0], bf1[0]);   // A2*B0
          mma16(par, af[1][mi], bf0[1], bf1[1]);   // A1*B1
          mma16(par, af[0][mi], bf0[2], bf1[2]);   // A0*B2
          mma16(par, af[1][mi], bf0[0], bf1[0]);   // A1*B0
          mma16(par, af[0][mi], bf0[1], bf1[1]);   // A0*B1
          mma16(par, af[0][mi], bf0[0], bf1[0]);   // A0*B0
          acc[mi][nj][0] += par[0];
          acc[mi][nj][1] += par[1];
          acc[mi][nj][2] += par[2];
          acc[mi][nj][3] += par[3];
        }
      }
    }
    if (c + 1 < C) commit((c + 1) & 1);
    __syncthreads();
  }

#pragma unroll
  for (int mi = 0; mi < 2; mi++)
#pragma unroll
    for (int nj = 0; nj < 8; nj++) {
      int r = wm + (mi << 4) + qr;
      int cc = wn + (nj << 3) + (qc << 1);
      *reinterpret_cast<float2*>(&Cb[r * HH + cc]) =
          make_float2(acc[mi][nj][0], acc[mi][nj][1]);
      *reinterpret_cast<float2*>(&Cb[(r + 8) * HH + cc]) =
          make_float2(acc[mi][nj][2], acc[mi][nj][3]);
    }
}

// ---------------- step kernels (R2-proven SIMT) ----------------

__global__ void copy_h_kernel(const float* __restrict__ x) {
  int i = blockIdx.x * 256 + threadIdx.x;
  g_h[i] = x[i];
}

template <int DIR>
__global__ void proj_kernel(const float* __restrict__ W, const float* __restrict__ bias) {
  const int m0 = blockIdx.y << 6;
  const int n0 = blockIdx.x << 6;
  float* dst = DIR ? g_out_st : g_in_st;
  auto aload = [&](int r, int k) {
    return *reinterpret_cast<const float4*>(&g_h[(m0 + r) * HH + k]);
  };
  auto bload = [&](int k, int n) {
    return *reinterpret_cast<const float4*>(&W[k * (HH * EE) + n0 + n]);
  };
  auto epi = [&](float (&acc)[4][4], int ty, int tx) {
#pragma unroll
    for (int i = 0; i < 4; i++) {
      int row = m0 + (ty << 2) + i;
      int b = row >> 9, n = row & (NN - 1);
#pragma unroll
      for (int j = 0; j < 4; j++) {
        int col = n0 + (tx << 2) + j;
        int e = col & 3, hh = col >> 2;
        dst[((b * EE + e) * NN + n) * HH + hh] = acc[i][j] + bias[col];
      }
    }
  };
  gemm64(aload, bload, epi, HH);
}

template <int MODE>
__global__ void gate_kernel(const float* __restrict__ W, const float* __restrict__ bias) {
  const int m0 = blockIdx.y << 6;
  const int n0 = blockIdx.x << 6;
  const float* p3 = (MODE == 2) ? g_rh : g_h;
  auto aload = [&](int r, int k) -> float4 {
    int row = m0 + r;
    const float* base;
    if (k < 128)       base = &g_ain[row * HH + k];
    else if (k < 256)  base = &g_aout[row * HH + (k - 128)];
    else               base = &p3[row * HH + (k - 256)];
    return *reinterpret_cast<const float4*>(base);
  };
  auto bload = [&](int k, int n) {
    return *reinterpret_cast<const float4*>(&W[k * HH + n0 + n]);
  };
  auto epi = [&](float (&acc)[4][4], int ty, int tx) {
#pragma unroll
    for (int i = 0; i < 4; i++) {
      int row = m0 + (ty << 2) + i;
#pragma unroll
      for (int j = 0; j < 4; j++) {
        int col = n0 + (tx << 2) + j;
        float v = acc[i][j] + bias[col];
        int idx = row * HH + col;
        if (MODE == 0) {
          g_z[idx] = sigmoidf_(v);
        } else if (MODE == 1) {
          g_rh[idx] = sigmoidf_(v) * g_h[idx];
        } else {
          float t = tanhf(v);
          float z = g_z[idx];
          g_h[idx] = (1.0f - z) * g_h[idx] + z * t;
        }
      }
    }
  };
  gemm64(aload, bload, epi, 3 * HH);
}

__global__ void final_kernel(const float* __restrict__ a,
                             const float* __restrict__ W1,
                             const float* __restrict__ b1,
                             const float* __restrict__ W2,
                             const float* __restrict__ b2,
                             float* __restrict__ out) {
  const int row = blockIdx.x;
  const int j = threadIdx.x;
  __shared__ float sh[HH + 1];
  __shared__ float red[HH];
  sh[j] = g_h[row * HH + j];
  if (j == 0) sh[HH] = a[row];
  __syncthreads();
  float acc = b1[j];
#pragma unroll 4
  for (int k = 0; k < HH + 1; k++) acc += sh[k] * W1[k * HH + j];
  red[j] = tanhf(acc) * W2[j];
  __syncthreads();
  for (int s = 64; s > 0; s >>= 1) {
    if (j < s) red[j] += red[j + s];
    __syncthreads();
  }
  if (j == 0) out[row] = red[0] + b2[0];
}

// ---------------- launch ----------------
extern "C" void kernel_launch(void* const* d_in, const int* in_sizes, int n_in,
                              void* d_out, int out_size) {
  const float* x     = (const float*)d_in[0];
  const float* a     = (const float*)d_in[1];
  const float* m     = (const float*)d_in[2];
  const float* W_in  = (const float*)d_in[3];
  const float* b_in  = (const float*)d_in[4];
  const float* W_out = (const float*)d_in[5];
  const float* b_out = (const float*)d_in[6];
  const float* W_z   = (const float*)d_in[7];
  const float* b_z   = (const float*)d_in[8];
  const float* W_r   = (const float*)d_in[9];
  const float* b_r   = (const float*)d_in[10];
  const float* W_t   = (const float*)d_in[11];
  const float* b_t   = (const float*)d_in[12];
  const float* W1    = (const float*)d_in[13];
  const float* b1    = (const float*)d_in[14];
  const float* W2    = (const float*)d_in[15];
  const float* b2    = (const float*)d_in[16];
  float* out = (float*)d_out;

  cudaFuncSetAttribute(einsum_tc8, cudaFuncAttributeMaxDynamicSharedMemorySize, EIN_SMEM);

  copy_h_kernel<<<NR * HH / 256, 256>>>(x);

  dim3 gp(8, 128);       // proj:   512/64 x 8192/64
  dim3 ge(4, 2 * BB);    // einsum: 512/128 x (b,dir)
  dim3 gg(2, 128);       // gates:  128/64 x 8192/64

  for (int s = 0; s < STEPS; s++) {
    proj_kernel<0><<<gp, 256>>>(W_in, b_in);
    proj_kernel<1><<<gp, 256>>>(W_out, b_out);
    einsum_tc8<<<ge, 256, EIN_SMEM>>>(m);
    gate_kernel<0><<<gg, 256>>>(W_z, b_z);
    gate_kernel<1><<<gg, 256>>>(W_r, b_r);
    gate_kernel<2><<<gg, 256>>>(W_t, b_t);
  }

  final_kernel<<<NR, 128>>>(a, W1, b1, W2, b2, out);
}

// round 11
// speedup vs baseline: 1.7473x; 1.7473x over previous
#include <cuda_runtime.h>
#include <cuda_bf16.h>
#include <math.h>

#define BB 16
#define NN 512
#define HH 128
#define EE 4
#define NE 2048          /* NN*EE */
#define NR 8192          /* BB*NN */
#define STEPS 5

// ---------------- scratch (device globals; no allocation) ----------------
__device__ float g_h[NR * HH];
__device__ float g_ain[NR * HH];
__device__ float g_aout[NR * HH];
__device__ float g_z[NR * HH];
__device__ float g_rh[NR * HH];
// bf16 split planes: x = p0 + p1 + p2 (exact 3-way split)
__device__ __nv_bfloat16 g_mA[2][BB][3][NN][NE];    // m planes [dir][b][p][n'][k]   201 MB
__device__ __nv_bfloat16 g_stB[2][BB][3][NE][HH];   // state planes [dir][b][p][m'][h] 50 MB

__device__ __forceinline__ float sigmoidf_(float v) { return 1.0f / (1.0f + expf(-v)); }

__device__ __forceinline__ void split3b(float x, __nv_bfloat16& b0, __nv_bfloat16& b1,
                                        __nv_bfloat16& b2) {
  b0 = __float2bfloat16_rn(x);
  float r1 = x - __bfloat162float(b0);
  b1 = __float2bfloat16_rn(r1);
  float r2 = r1 - __bfloat162float(b1);
  b2 = __float2bfloat16_rn(r2);
}

// ---------------- PTX helpers (all baseline sm_80+, legal on compute_103) ----
__device__ __forceinline__ void mma16(float (&d)[4], const unsigned (&a)[4],
                                      unsigned b0, unsigned b1) {
  asm volatile(
      "mma.sync.aligned.m16n8k16.row.col.f32.bf16.bf16.f32 "
      "{%0,%1,%2,%3}, {%4,%5,%6,%7}, {%8,%9}, {%0,%1,%2,%3};"
      : "+f"(d[0]), "+f"(d[1]), "+f"(d[2]), "+f"(d[3])
      : "r"(a[0]), "r"(a[1]), "r"(a[2]), "r"(a[3]), "r"(b0), "r"(b1));
}
__device__ __forceinline__ void ldm_x4(unsigned* r, unsigned addr) {
  asm volatile("ldmatrix.sync.aligned.m8n8.x4.shared.b16 {%0,%1,%2,%3}, [%4];"
               : "=r"(r[0]), "=r"(r[1]), "=r"(r[2]), "=r"(r[3]) : "r"(addr));
}
__device__ __forceinline__ void ldm_x4t(unsigned& r0, unsigned& r1, unsigned& r2,
                                        unsigned& r3, unsigned addr) {
  asm volatile("ldmatrix.sync.aligned.m8n8.x4.trans.shared.b16 {%0,%1,%2,%3}, [%4];"
               : "=r"(r0), "=r"(r1), "=r"(r2), "=r"(r3) : "r"(addr));
}
__device__ __forceinline__ void cpa16(unsigned dst, const void* src) {
  asm volatile("cp.async.cg.shared.global [%0], [%1], 16;" :: "r"(dst), "l"(src));
}
#define CP_COMMIT() asm volatile("cp.async.commit_group;" ::: "memory")
#define CP_WAIT1()  asm volatile("cp.async.wait_group 1;" ::: "memory")

// ---------------- one-time m split:  m -> 6 bf16 planes ----------------
__global__ void split_m_kernel(const float* __restrict__ mm) {
  long long i = (long long)blockIdx.x * 256 + threadIdx.x;   // over BB*NN*2*NE
  int j = (int)(i & 4095);
  long long bn = i >> 12;
  int n = (int)(bn & 511);
  int b = (int)(bn >> 9);
  int dir = j >> 11, k = j & 2047;
  float v = mm[i];
  __nv_bfloat16 p0, p1, p2;
  split3b(v, p0, p1, p2);
  g_mA[dir][b][0][n][k] = p0;
  g_mA[dir][b][1][n][k] = p1;
  g_mA[dir][b][2][n][k] = p2;
}

// ---------------- R2-proven fp32 SIMT GEMM core (proj/gates) ----------------
template <class ALoad, class BLoad, class Epi>
__device__ __forceinline__ void gemm64(ALoad aload, BLoad bload, Epi epi, int K) {
  __shared__ __align__(16) float As[16][68];
  __shared__ __align__(16) float Bs[16][64];
  float acc[4][4] = {};
  const int tid = threadIdx.x;
  const int tx = tid & 15, ty = tid >> 4;
  const int ar = tid >> 2, ak = (tid & 3) << 2;
  const int bk = tid >> 4, bn = (tid & 15) << 2;

  for (int k0 = 0; k0 < K; k0 += 16) {
    float4 av = aload(ar, k0 + ak);
    As[ak + 0][ar] = av.x;
    As[ak + 1][ar] = av.y;
    As[ak + 2][ar] = av.z;
    As[ak + 3][ar] = av.w;
    float4 bv = bload(k0 + bk, bn);
    *reinterpret_cast<float4*>(&Bs[bk][bn]) = bv;
    __syncthreads();
#pragma unroll
    for (int kk = 0; kk < 16; kk++) {
      float4 a4 = *reinterpret_cast<const float4*>(&As[kk][ty << 2]);
      float4 b4 = *reinterpret_cast<const float4*>(&Bs[kk][tx << 2]);
      float a[4] = {a4.x, a4.y, a4.z, a4.w};
      float b[4] = {b4.x, b4.y, b4.z, b4.w};
#pragma unroll
      for (int i = 0; i < 4; i++)
#pragma unroll
        for (int j = 0; j < 4; j++) acc[i][j] += a[i] * b[j];
    }
    __syncthreads();
  }
  epi(acc, ty, tx);
}

__global__ void copy_h_kernel(const float* __restrict__ x) {
  int i = blockIdx.x * 256 + threadIdx.x;
  g_h[i] = x[i];
}

// y = h @ W (+ bias) -> states written DIRECTLY as 3 bf16 planes
// y[b,n, hh*E+e] -> planes[dir][b][p][e*N+n][hh]
template <int DIR>
__global__ void proj_kernel(const float* __restrict__ W, const float* __restrict__ bias) {
  const int m0 = blockIdx.y << 6;
  const int n0 = blockIdx.x << 6;
  auto aload = [&](int r, int k) {
    return *reinterpret_cast<const float4*>(&g_h[(m0 + r) * HH + k]);
  };
  auto bload = [&](int k, int n) {
    return *reinterpret_cast<const float4*>(&W[k * (HH * EE) + n0 + n]);
  };
  auto epi = [&](float (&acc)[4][4], int ty, int tx) {
#pragma unroll
    for (int i = 0; i < 4; i++) {
      int row = m0 + (ty << 2) + i;
      int b = row >> 9, n = row & (NN - 1);
#pragma unroll
      for (int j = 0; j < 4; j++) {
        int col = n0 + (tx << 2) + j;
        int e = col & 3, hh = col >> 2;
        float v = acc[i][j] + bias[col];
        int mp = e * NN + n;
        __nv_bfloat16 p0, p1, p2;
        split3b(v, p0, p1, p2);
        g_stB[DIR][b][0][mp][hh] = p0;
        g_stB[DIR][b][1][mp][hh] = p1;
        g_stB[DIR][b][2][mp][hh] = p2;
      }
    }
  };
  gemm64(aload, bload, epi, HH);
}

// ---------------- einsum: cp.async + ldmatrix + 6-term bf16 MMA ----------------
// C[128,128] per CTA: A = m planes [n'][k] (row-major), B = state planes [k][h].
// K = 2048 in 64 chunks of 32. 3-stage cp.async ring. 8 warps (4M x 2N), tile 32x64.
#define A_ROWB 80                      /* bytes per A smem row (64 data + 16 pad) */
#define A_PLB  (128 * A_ROWB)          /* 10240 B */
#define B_ROWB 272                     /* bytes per B smem k-row (256 + 16 pad) */
#define B_PLB  (32 * B_ROWB)           /* 8704 B */
#define A_STB  (3 * A_PLB)             /* 30720 B */
#define STAGE_B (A_STB + 3 * B_PLB)    /* 56832 B */
#define EIN_SMEM (3 * STAGE_B)         /* 170496 B */

__global__ __launch_bounds__(256, 1) void einsum_cp() {
  extern __shared__ __align__(16) char sm[];
  const unsigned su = (unsigned)__cvta_generic_to_shared(sm);
  const int tid = threadIdx.x, lane = tid & 31, wid = tid >> 5;
  const int wm = (wid & 3) << 5;     // warp M offset
  const int wn = (wid >> 2) << 6;    // warp N offset

  const int zz = blockIdx.y, dir = zz & 1, b = zz >> 1;
  const int m0 = blockIdx.x << 7;
  const __nv_bfloat16* Ag = &g_mA[dir][b][0][0][0];   // plane stride NN*NE
  const __nv_bfloat16* Bg = &g_stB[dir][b][0][0][0];  // plane stride NE*HH

  auto copy = [&](int c, int s) {
    const unsigned sb = su + s * STAGE_B;
#pragma unroll
    for (int i = 0; i < 6; i++) {            // A: 3 planes x 128 rows x 4 segs (24576 B)
      int u = tid + (i << 8);
      int p = u >> 9, rem = u & 511;
      int r = rem >> 2, seg = rem & 3;
      cpa16(sb + p * A_PLB + r * A_ROWB + seg * 16,
            Ag + (size_t)p * (NN * NE) + (size_t)(m0 + r) * NE + (c << 5) + seg * 8);
    }
#pragma unroll
    for (int i = 0; i < 6; i++) {            // B: 3 planes x 32 k-rows x 16 segs (24576 B)
      int u = tid + (i << 8);
      int p = u >> 9, rem = u & 511;
      int r = rem >> 4, seg = rem & 15;      // FIXED: full 256B per k-row
      cpa16(sb + A_STB + p * B_PLB + r * B_ROWB + seg * 16,
            Bg + (size_t)p * (NE * HH) + (size_t)((c << 5) + r) * HH + seg * 8);
    }
  };

  float acc[2][8][4] = {};

  copy(0, 0); CP_COMMIT();
  copy(1, 1); CP_COMMIT();

  const int la = lane & 7, lb = (lane >> 3) & 1, lc = lane >> 4;

  for (int c = 0; c < 64; c++) {
    CP_WAIT1();
    __syncthreads();
    if (c + 2 < 64) copy(c + 2, (c + 2) % 3);
    CP_COMMIT();

    const unsigned Ab = su + (c % 3) * STAGE_B;
    const unsigned Bb = Ab + A_STB;
#pragma unroll
    for (int ks = 0; ks < 2; ks++) {
      unsigned af[3][2][4];
#pragma unroll
      for (int p = 0; p < 3; p++)
#pragma unroll
        for (int mi = 0; mi < 2; mi++)
          ldm_x4(af[p][mi],
                 Ab + p * A_PLB + (wm + (mi << 4) + la + lb * 8) * A_ROWB + ks * 32 + lc * 16);

      unsigned bfr[3][8][2];
#pragma unroll
      for (int p = 0; p < 3; p++)
#pragma unroll
        for (int g4 = 0; g4 < 4; g4++)
          ldm_x4t(bfr[p][2 * g4][0], bfr[p][2 * g4][1],
                  bfr[p][2 * g4 + 1][0], bfr[p][2 * g4 + 1][1],
                  Bb + p * B_PLB + ((ks << 4) + la + lb * 8) * B_ROWB +
                      (wn + (g4 << 4) + lc * 8) * 2);

#pragma unroll
      for (int nj = 0; nj < 8; nj++)
#pragma unroll
        for (int mi = 0; mi < 2; mi++) {
          // 6 terms, smallest first, into zeroed partial; RN-fold into master.
          float par[4] = {0.f, 0.f, 0.f, 0.f};
          mma16(par, af[1][mi], bfr[1][nj][0], bfr[1][nj][1]);   // A1*B1
          mma16(par, af[0][mi], bfr[2][nj][0], bfr[2][nj][1]);   // A0*B2
          mma16(par, af[2][mi], bfr[0][nj][0], bfr[0][nj][1]);   // A2*B0
          mma16(par, af[1][mi], bfr[0][nj][0], bfr[0][nj][1]);   // A1*B0
          mma16(par, af[0][mi], bfr[1][nj][0], bfr[1][nj][1]);   // A0*B1
          mma16(par, af[0][mi], bfr[0][nj][0], bfr[0][nj][1]);   // A0*B0
          acc[mi][nj][0] += par[0];
          acc[mi][nj][1] += par[1];
          acc[mi][nj][2] += par[2];
          acc[mi][nj][3] += par[3];
        }
    }
    __syncthreads();
  }

  float* Cb = (dir ? g_aout : g_ain) + (size_t)(b * NN + m0) * HH;
  const int qr = lane >> 2, qc = lane & 3;
#pragma unroll
  for (int mi = 0; mi < 2; mi++)
#pragma unroll
    for (int nj = 0; nj < 8; nj++) {
      int r = wm + (mi << 4) + qr;
      int cc = wn + (nj << 3) + (qc << 1);
      *reinterpret_cast<float2*>(&Cb[r * HH + cc]) =
          make_float2(acc[mi][nj][0], acc[mi][nj][1]);
      *reinterpret_cast<float2*>(&Cb[(r + 8) * HH + cc]) =
          make_float2(acc[mi][nj][2], acc[mi][nj][3]);
    }
}

// Gate GEMMs (R2-proven SIMT)
template <int MODE>
__global__ void gate_kernel(const float* __restrict__ W, const float* __restrict__ bias) {
  const int m0 = blockIdx.y << 6;
  const int n0 = blockIdx.x << 6;
  const float* p3 = (MODE == 2) ? g_rh : g_h;
  auto aload = [&](int r, int k) -> float4 {
    int row = m0 + r;
    const float* base;
    if (k < 128)       base = &g_ain[row * HH + k];
    else if (k < 256)  base = &g_aout[row * HH + (k - 128)];
    else               base = &p3[row * HH + (k - 256)];
    return *reinterpret_cast<const float4*>(base);
  };
  auto bload = [&](int k, int n) {
    return *reinterpret_cast<const float4*>(&W[k * HH + n0 + n]);
  };
  auto epi = [&](float (&acc)[4][4], int ty, int tx) {
#pragma unroll
    for (int i = 0; i < 4; i++) {
      int row = m0 + (ty << 2) + i;
#pragma unroll
      for (int j = 0; j < 4; j++) {
        int col = n0 + (tx << 2) + j;
        float v = acc[i][j] + bias[col];
        int idx = row * HH + col;
        if (MODE == 0) {
          g_z[idx] = sigmoidf_(v);
        } else if (MODE == 1) {
          g_rh[idx] = sigmoidf_(v) * g_h[idx];
        } else {
          float t = tanhf(v);
          float z = g_z[idx];
          g_h[idx] = (1.0f - z) * g_h[idx] + z * t;
        }
      }
    }
  };
  gemm64(aload, bload, epi, 3 * HH);
}

__global__ void final_kernel(const float* __restrict__ a,
                             const float* __restrict__ W1,
                             const float* __restrict__ b1,
                             const float* __restrict__ W2,
                             const float* __restrict__ b2,
                             float* __restrict__ out) {
  const int row = blockIdx.x;
  const int j = threadIdx.x;
  __shared__ float sh[HH + 1];
  __shared__ float red[HH];
  sh[j] = g_h[row * HH + j];
  if (j == 0) sh[HH] = a[row];
  __syncthreads();
  float acc = b1[j];
#pragma unroll 4
  for (int k = 0; k < HH + 1; k++) acc += sh[k] * W1[k * HH + j];
  red[j] = tanhf(acc) * W2[j];
  __syncthreads();
  for (int s = 64; s > 0; s >>= 1) {
    if (j < s) red[j] += red[j + s];
    __syncthreads();
  }
  if (j == 0) out[row] = red[0] + b2[0];
}

// ---------------- launch ----------------
extern "C" void kernel_launch(void* const* d_in, const int* in_sizes, int n_in,
                              void* d_out, int out_size) {
  const float* x     = (const float*)d_in[0];
  const float* a     = (const float*)d_in[1];
  const float* m     = (const float*)d_in[2];
  const float* W_in  = (const float*)d_in[3];
  const float* b_in  = (const float*)d_in[4];
  const float* W_out = (const float*)d_in[5];
  const float* b_out = (const float*)d_in[6];
  const float* W_z   = (const float*)d_in[7];
  const float* b_z   = (const float*)d_in[8];
  const float* W_r   = (const float*)d_in[9];
  const float* b_r   = (const float*)d_in[10];
  const float* W_t   = (const float*)d_in[11];
  const float* b_t   = (const float*)d_in[12];
  const float* W1    = (const float*)d_in[13];
  const float* b1    = (const float*)d_in[14];
  const float* W2    = (const float*)d_in[15];
  const float* b2    = (const float*)d_in[16];
  float* out = (float*)d_out;

  cudaFuncSetAttribute(einsum_cp, cudaFuncAttributeMaxDynamicSharedMemorySize, EIN_SMEM);

  copy_h_kernel<<<NR * HH / 256, 256>>>(x);
  split_m_kernel<<<(BB * NN * 2 * NE) / 256, 256>>>(m);

  dim3 gp(8, 128);       // proj:   512/64 x 8192/64
  dim3 ge(4, 2 * BB);    // einsum: 512/128 x (b,dir)
  dim3 gg(2, 128);       // gates:  128/64 x 8192/64

  for (int s = 0; s < STEPS; s++) {
    proj_kernel<0><<<gp, 256>>>(W_in, b_in);
    proj_kernel<1><<<gp, 256>>>(W_out, b_out);
    einsum_cp<<<ge, 256, EIN_SMEM>>>();
    gate_kernel<0><<<gg, 256>>>(W_z, b_z);
    gate_kernel<1><<<gg, 256>>>(W_r, b_r);
    gate_kernel<2><<<gg, 256>>>(W_t, b_t);
  }

  final_kernel<<<NR, 128>>>(a, W1, b1, W2, b2, out);
}

// round 12
// speedup vs baseline: 1.8213x; 1.0424x over previous
#include <cuda_runtime.h>
#include <cuda_bf16.h>
#include <math.h>

#define BB 16
#define NN 512
#define HH 128
#define EE 4
#define NE 2048          /* NN*EE */
#define NR 8192          /* BB*NN */
#define STEPS 5

// ---------------- scratch (device globals; no allocation) ----------------
__device__ float g_h[NR * HH];
__device__ float g_ain[NR * HH];
__device__ float g_aout[NR * HH];
__device__ float g_z[NR * HH];
__device__ float g_rh[NR * HH];
// bf16 split planes: x = p0 + p1 + p2 (exact 3-way split)
__device__ __nv_bfloat16 g_mA[2][BB][3][NN][NE];    // m planes [dir][b][p][n'][k]
__device__ __nv_bfloat16 g_stB[2][BB][3][NE][HH];   // state planes [dir][b][p][m'][h]

__device__ __forceinline__ float sigmoidf_(float v) { return 1.0f / (1.0f + expf(-v)); }

__device__ __forceinline__ void split3b(float x, __nv_bfloat16& b0, __nv_bfloat16& b1,
                                        __nv_bfloat16& b2) {
  b0 = __float2bfloat16_rn(x);
  float r1 = x - __bfloat162float(b0);
  b1 = __float2bfloat16_rn(r1);
  float r2 = r1 - __bfloat162float(b1);
  b2 = __float2bfloat16_rn(r2);
}

// ---------------- PTX helpers (all baseline sm_80+, legal on compute_103) ----
__device__ __forceinline__ void mma16(float (&d)[4], const unsigned (&a)[4],
                                      unsigned b0, unsigned b1) {
  asm volatile(
      "mma.sync.aligned.m16n8k16.row.col.f32.bf16.bf16.f32 "
      "{%0,%1,%2,%3}, {%4,%5,%6,%7}, {%8,%9}, {%0,%1,%2,%3};"
      : "+f"(d[0]), "+f"(d[1]), "+f"(d[2]), "+f"(d[3])
      : "r"(a[0]), "r"(a[1]), "r"(a[2]), "r"(a[3]), "r"(b0), "r"(b1));
}
__device__ __forceinline__ void ldm_x4(unsigned* r, unsigned addr) {
  asm volatile("ldmatrix.sync.aligned.m8n8.x4.shared.b16 {%0,%1,%2,%3}, [%4];"
               : "=r"(r[0]), "=r"(r[1]), "=r"(r[2]), "=r"(r[3]) : "r"(addr));
}
__device__ __forceinline__ void ldm_x4t(unsigned& r0, unsigned& r1, unsigned& r2,
                                        unsigned& r3, unsigned addr) {
  asm volatile("ldmatrix.sync.aligned.m8n8.x4.trans.shared.b16 {%0,%1,%2,%3}, [%4];"
               : "=r"(r0), "=r"(r1), "=r"(r2), "=r"(r3) : "r"(addr));
}
__device__ __forceinline__ void cpa16(unsigned dst, const void* src) {
  asm volatile("cp.async.cg.shared.global [%0], [%1], 16;" :: "r"(dst), "l"(src));
}
#define CP_COMMIT() asm volatile("cp.async.commit_group;" ::: "memory")
#define CP_WAIT0()  asm volatile("cp.async.wait_group 0;" ::: "memory")

// ---------------- one-time m split:  m -> 6 bf16 planes ----------------
__global__ void split_m_kernel(const float* __restrict__ mm) {
  long long i = (long long)blockIdx.x * 256 + threadIdx.x;   // over BB*NN*2*NE
  int j = (int)(i & 4095);
  long long bn = i >> 12;
  int n = (int)(bn & 511);
  int b = (int)(bn >> 9);
  int dir = j >> 11, k = j & 2047;
  float v = mm[i];
  __nv_bfloat16 p0, p1, p2;
  split3b(v, p0, p1, p2);
  g_mA[dir][b][0][n][k] = p0;
  g_mA[dir][b][1][n][k] = p1;
  g_mA[dir][b][2][n][k] = p2;
}

// ---------------- R2-proven fp32 SIMT GEMM core (proj/gates) ----------------
template <class ALoad, class BLoad, class Epi>
__device__ __forceinline__ void gemm64(ALoad aload, BLoad bload, Epi epi, int K) {
  __shared__ __align__(16) float As[16][68];
  __shared__ __align__(16) float Bs[16][64];
  float acc[4][4] = {};
  const int tid = threadIdx.x;
  const int tx = tid & 15, ty = tid >> 4;
  const int ar = tid >> 2, ak = (tid & 3) << 2;
  const int bk = tid >> 4, bn = (tid & 15) << 2;

  for (int k0 = 0; k0 < K; k0 += 16) {
    float4 av = aload(ar, k0 + ak);
    As[ak + 0][ar] = av.x;
    As[ak + 1][ar] = av.y;
    As[ak + 2][ar] = av.z;
    As[ak + 3][ar] = av.w;
    float4 bv = bload(k0 + bk, bn);
    *reinterpret_cast<float4*>(&Bs[bk][bn]) = bv;
    __syncthreads();
#pragma unroll
    for (int kk = 0; kk < 16; kk++) {
      float4 a4 = *reinterpret_cast<const float4*>(&As[kk][ty << 2]);
      float4 b4 = *reinterpret_cast<const float4*>(&Bs[kk][tx << 2]);
      float a[4] = {a4.x, a4.y, a4.z, a4.w};
      float b[4] = {b4.x, b4.y, b4.z, b4.w};
#pragma unroll
      for (int i = 0; i < 4; i++)
#pragma unroll
        for (int j = 0; j < 4; j++) acc[i][j] += a[i] * b[j];
    }
    __syncthreads();
  }
  epi(acc, ty, tx);
}

__global__ void copy_h_kernel(const float* __restrict__ x) {
  int i = blockIdx.x * 256 + threadIdx.x;
  g_h[i] = x[i];
}

// y = h @ W (+ bias) -> states written DIRECTLY as 3 bf16 planes
template <int DIR>
__global__ void proj_kernel(const float* __restrict__ W, const float* __restrict__ bias) {
  const int m0 = blockIdx.y << 6;
  const int n0 = blockIdx.x << 6;
  auto aload = [&](int r, int k) {
    return *reinterpret_cast<const float4*>(&g_h[(m0 + r) * HH + k]);
  };
  auto bload = [&](int k, int n) {
    return *reinterpret_cast<const float4*>(&W[k * (HH * EE) + n0 + n]);
  };
  auto epi = [&](float (&acc)[4][4], int ty, int tx) {
#pragma unroll
    for (int i = 0; i < 4; i++) {
      int row = m0 + (ty << 2) + i;
      int b = row >> 9, n = row & (NN - 1);
#pragma unroll
      for (int j = 0; j < 4; j++) {
        int col = n0 + (tx << 2) + j;
        int e = col & 3, hh = col >> 2;
        float v = acc[i][j] + bias[col];
        int mp = e * NN + n;
        __nv_bfloat16 p0, p1, p2;
        split3b(v, p0, p1, p2);
        g_stB[DIR][b][0][mp][hh] = p0;
        g_stB[DIR][b][1][mp][hh] = p1;
        g_stB[DIR][b][2][mp][hh] = p2;
      }
    }
  };
  gemm64(aload, bload, epi, HH);
}

// ---------------- einsum: cp.async + ldmatrix + 6-term bf16 MMA ----------------
// K = 2048 in 32 chunks of 64. 2-stage cp.async ring, ONE sync per chunk.
// 8 warps (4M x 2N), warp tile 32x64, CTA tile 128x128.
#define A_ROWB 144                     /* bytes per A smem row (128 data + 16 pad) */
#define A_PLB  (128 * A_ROWB)          /* 18432 B */
#define B_ROWB 272                     /* bytes per B smem k-row (256 + 16 pad) */
#define B_PLB  (64 * B_ROWB)           /* 17408 B */
#define A_STB  (3 * A_PLB)             /* 55296 B */
#define STAGE_B (A_STB + 3 * B_PLB)    /* 107520 B */
#define EIN_SMEM (2 * STAGE_B)         /* 215040 B */

__global__ __launch_bounds__(256, 1) void einsum_cp() {
  extern __shared__ __align__(16) char sm[];
  const unsigned su = (unsigned)__cvta_generic_to_shared(sm);
  const int tid = threadIdx.x, lane = tid & 31, wid = tid >> 5;
  const int wm = (wid & 3) << 5;     // warp M offset
  const int wn = (wid >> 2) << 6;    // warp N offset

  const int zz = blockIdx.y, dir = zz & 1, b = zz >> 1;
  const int m0 = blockIdx.x << 7;
  const __nv_bfloat16* Ag = &g_mA[dir][b][0][0][0];   // plane stride NN*NE
  const __nv_bfloat16* Bg = &g_stB[dir][b][0][0][0];  // plane stride NE*HH

  auto copy = [&](int c, int s) {
    const unsigned sb = su + s * STAGE_B;
#pragma unroll
    for (int i = 0; i < 12; i++) {           // A: 3 planes x 128 rows x 8 segs
      int u = tid + (i << 8);
      int p = u >> 10, rem = u & 1023;
      int r = rem >> 3, seg = rem & 7;
      cpa16(sb + p * A_PLB + r * A_ROWB + seg * 16,
            Ag + (size_t)p * (NN * NE) + (size_t)(m0 + r) * NE + (c << 6) + seg * 8);
    }
#pragma unroll
    for (int i = 0; i < 12; i++) {           // B: 3 planes x 64 k-rows x 16 segs
      int u = tid + (i << 8);
      int p = u >> 10, rem = u & 1023;
      int r = rem >> 4, seg = rem & 15;
      cpa16(sb + A_STB + p * B_PLB + r * B_ROWB + seg * 16,
            Bg + (size_t)p * (NE * HH) + (size_t)((c << 6) + r) * HH + seg * 8);
    }
  };

  float acc[2][8][4] = {};

  copy(0, 0); CP_COMMIT();

  const int la = lane & 7, lb = (lane >> 3) & 1, lc = lane >> 4;

  for (int c = 0; c < 32; c++) {
    CP_WAIT0();
    __syncthreads();                 // c's data visible; all warps done reading stage (c+1)&1
    if (c + 1 < 32) { copy(c + 1, (c + 1) & 1); CP_COMMIT(); }

    const unsigned Ab = su + (c & 1) * STAGE_B;
    const unsigned Bb = Ab + A_STB;
#pragma unroll
    for (int ks = 0; ks < 4; ks++) {
      unsigned af[3][2][4];
#pragma unroll
      for (int p = 0; p < 3; p++)
#pragma unroll
        for (int mi = 0; mi < 2; mi++)
          ldm_x4(af[p][mi],
                 Ab + p * A_PLB + (wm + (mi << 4) + la + lb * 8) * A_ROWB + ks * 32 + lc * 16);

      unsigned bfr[3][8][2];
#pragma unroll
      for (int p = 0; p < 3; p++)
#pragma unroll
        for (int g4 = 0; g4 < 4; g4++)
          ldm_x4t(bfr[p][2 * g4][0], bfr[p][2 * g4][1],
                  bfr[p][2 * g4 + 1][0], bfr[p][2 * g4 + 1][1],
                  Bb + p * B_PLB + ((ks << 4) + la + lb * 8) * B_ROWB +
                      (wn + (g4 << 4) + lc * 8) * 2);

#pragma unroll
      for (int nj = 0; nj < 8; nj++)
#pragma unroll
        for (int mi = 0; mi < 2; mi++) {
          // 6 terms, smallest first, into zeroed partial; RN-fold into master.
          float par[4] = {0.f, 0.f, 0.f, 0.f};
          mma16(par, af[1][mi], bfr[1][nj][0], bfr[1][nj][1]);   // A1*B1
          mma16(par, af[0][mi], bfr[2][nj][0], bfr[2][nj][1]);   // A0*B2
          mma16(par, af[2][mi], bfr[0][nj][0], bfr[0][nj][1]);   // A2*B0
          mma16(par, af[1][mi], bfr[0][nj][0], bfr[0][nj][1]);   // A1*B0
          mma16(par, af[0][mi], bfr[1][nj][0], bfr[1][nj][1]);   // A0*B1
          mma16(par, af[0][mi], bfr[0][nj][0], bfr[0][nj][1]);   // A0*B0
          acc[mi][nj][0] += par[0];
          acc[mi][nj][1] += par[1];
          acc[mi][nj][2] += par[2];
          acc[mi][nj][3] += par[3];
        }
    }
  }

  float* Cb = (dir ? g_aout : g_ain) + (size_t)(b * NN + m0) * HH;
  const int qr = lane >> 2, qc = lane & 3;
#pragma unroll
  for (int mi = 0; mi < 2; mi++)
#pragma unroll
    for (int nj = 0; nj < 8; nj++) {
      int r = wm + (mi << 4) + qr;
      int cc = wn + (nj << 3) + (qc << 1);
      *reinterpret_cast<float2*>(&Cb[r * HH + cc]) =
          make_float2(acc[mi][nj][0], acc[mi][nj][1]);
      *reinterpret_cast<float2*>(&Cb[(r + 8) * HH + cc]) =
          make_float2(acc[mi][nj][2], acc[mi][nj][3]);
    }
}

// Gate GEMMs (R2-proven SIMT)
template <int MODE>
__global__ void gate_kernel(const float* __restrict__ W, const float* __restrict__ bias) {
  const int m0 = blockIdx.y << 6;
  const int n0 = blockIdx.x << 6;
  const float* p3 = (MODE == 2) ? g_rh : g_h;
  auto aload = [&](int r, int k) -> float4 {
    int row = m0 + r;
    const float* base;
    if (k < 128)       base = &g_ain[row * HH + k];
    else if (k < 256)  base = &g_aout[row * HH + (k - 128)];
    else               base = &p3[row * HH + (k - 256)];
    return *reinterpret_cast<const float4*>(base);
  };
  auto bload = [&](int k, int n) {
    return *reinterpret_cast<const float4*>(&W[k * HH + n0 + n]);
  };
  auto epi = [&](float (&acc)[4][4], int ty, int tx) {
#pragma unroll
    for (int i = 0; i < 4; i++) {
      int row = m0 + (ty << 2) + i;
#pragma unroll
      for (int j = 0; j < 4; j++) {
        int col = n0 + (tx << 2) + j;
        float v = acc[i][j] + bias[col];
        int idx = row * HH + col;
        if (MODE == 0) {
          g_z[idx] = sigmoidf_(v);
        } else if (MODE == 1) {
          g_rh[idx] = sigmoidf_(v) * g_h[idx];
        } else {
          float t = tanhf(v);
          float z = g_z[idx];
          g_h[idx] = (1.0f - z) * g_h[idx] + z * t;
        }
      }
    }
  };
  gemm64(aload, bload, epi, 3 * HH);
}

__global__ void final_kernel(const float* __restrict__ a,
                             const float* __restrict__ W1,
                             const float* __restrict__ b1,
                             const float* __restrict__ W2,
                             const float* __restrict__ b2,
                             float* __restrict__ out) {
  const int row = blockIdx.x;
  const int j = threadIdx.x;
  __shared__ float sh[HH + 1];
  __shared__ float red[HH];
  sh[j] = g_h[row * HH + j];
  if (j == 0) sh[HH] = a[row];
  __syncthreads();
  float acc = b1[j];
#pragma unroll 4
  for (int k = 0; k < HH + 1; k++) acc += sh[k] * W1[k * HH + j];
  red[j] = tanhf(acc) * W2[j];
  __syncthreads();
  for (int s = 64; s > 0; s >>= 1) {
    if (j < s) red[j] += red[j + s];
    __syncthreads();
  }
  if (j == 0) out[row] = red[0] + b2[0];
}

// ---------------- launch ----------------
extern "C" void kernel_launch(void* const* d_in, const int* in_sizes, int n_in,
                              void* d_out, int out_size) {
  const float* x     = (const float*)d_in[0];
  const float* a     = (const float*)d_in[1];
  const float* m     = (const float*)d_in[2];
  const float* W_in  = (const float*)d_in[3];
  const float* b_in  = (const float*)d_in[4];
  const float* W_out = (const float*)d_in[5];
  const float* b_out = (const float*)d_in[6];
  const float* W_z   = (const float*)d_in[7];
  const float* b_z   = (const float*)d_in[8];
  const float* W_r   = (const float*)d_in[9];
  const float* b_r   = (const float*)d_in[10];
  const float* W_t   = (const float*)d_in[11];
  const float* b_t   = (const float*)d_in[12];
  const float* W1    = (const float*)d_in[13];
  const float* b1    = (const float*)d_in[14];
  const float* W2    = (const float*)d_in[15];
  const float* b2    = (const float*)d_in[16];
  float* out = (float*)d_out;

  cudaFuncSetAttribute(einsum_cp, cudaFuncAttributeMaxDynamicSharedMemorySize, EIN_SMEM);

  copy_h_kernel<<<NR * HH / 256, 256>>>(x);
  split_m_kernel<<<(BB * NN * 2 * NE) / 256, 256>>>(m);

  dim3 gp(8, 128);       // proj:   512/64 x 8192/64
  dim3 ge(4, 2 * BB);    // einsum: 512/128 x (b,dir)
  dim3 gg(2, 128);       // gates:  128/64 x 8192/64

  for (int s = 0; s < STEPS; s++) {
    proj_kernel<0><<<gp, 256>>>(W_in, b_in);
    proj_kernel<1><<<gp, 256>>>(W_out, b_out);
    einsum_cp<<<ge, 256, EIN_SMEM>>>();
    gate_kernel<0><<<gg, 256>>>(W_z, b_z);
    gate_kernel<1><<<gg, 256>>>(W_r, b_r);
    gate_kernel<2><<<gg, 256>>>(W_t, b_t);
  }

  final_kernel<<<NR, 128>>>(a, W1, b1, W2, b2, out);
}